// round 1
// baseline (speedup 1.0000x reference)
#include <cuda_runtime.h>

// DKVMN forward, restructured:
//   k_m1    : M1[h][m] = sum_v W_f[h][v] * V[m][v]            (512x50)
//   k_main  : per 64 table indices: gather embed, logits GEMM, softmax,
//             fused H = [W_f_k | M1] @ [e; corr] + b, pred = sigmoid(w_p . relu(H) + b_p)
//             -> g_pred[50001]
//   k_gather: out[j] = g_pred[q[j]]                            (262144)

#define NQ   50001
#define DK   128
#define DV   256
#define MM   50
#define HH   512
#define FF   384
#define TI   64     // indices per block
#define KT   192    // unified k: 128 (embed) + 50 (corr) + 14 zero pad

#define SB_STRIDE 68
#define SA_STRIDE 196
#define SK_STRIDE 132
#define OFF_B   0
#define OFF_A   (192 * SB_STRIDE)            // 13056 floats
#define OFF_RED (OFF_A + 64 * SA_STRIDE)     // 13056 + 12544 = 25600
#define SMEM_FLOATS (OFF_RED + 16 * SB_STRIDE) // 26688 floats = 106752 B

__device__ float g_M1[HH * MM];
__device__ float g_pred[NQ];

// ---------------------------------------------------------------- kernel 0
__global__ void k_m1(const float* __restrict__ Wf, const float* __restrict__ V) {
    int t = blockIdx.x * blockDim.x + threadIdx.x;
    if (t >= HH * MM) return;
    int h = t / MM, m = t - h * MM;
    const float* wr = Wf + h * FF;       // value part: cols [0,256)
    const float* vr = V + m * DV;
    float s = 0.f;
#pragma unroll 8
    for (int v = 0; v < DV; v++) s += wr[v] * vr[v];
    g_M1[t] = s;
}

// ---------------------------------------------------------------- kernel 1
__global__ void __launch_bounds__(256, 2) k_main(
    const float* __restrict__ embed, const float* __restrict__ Kmem,
    const float* __restrict__ Wf,    const float* __restrict__ bf,
    const float* __restrict__ Wp,    const float* __restrict__ bp)
{
    extern __shared__ float sm[];
    const int tid  = threadIdx.x;
    const int base = blockIdx.x * TI;

    // ---- gather embed tile into sB[k][i] (rows 0..127)
    for (int e = tid; e < TI * DK; e += 256) {
        int i = e >> 7, k = e & 127;
        int r = base + i; if (r >= NQ) r = NQ - 1;
        sm[OFF_B + k * SB_STRIDE + i] = embed[r * DK + k];
    }
    // ---- zero sK region (rows 0..63), then load key_memory rows 0..49
    for (int e = tid; e < 64 * SK_STRIDE; e += 256) sm[OFF_A + e] = 0.f;
    __syncthreads();
    for (int e = tid; e < MM * DK; e += 256) {
        int m = e >> 7, k = e & 127;
        sm[OFF_A + m * SK_STRIDE + k] = Kmem[e];
    }
    __syncthreads();

    const int tx = tid & 15, ty = tid >> 4;
    const int i0 = tx * 4;

    // ---- GEMM1: logits[m][i] = sum_k K[m][k] * E[k][i]   (m padded to 64)
    {
        const int m0 = ty * 4;
        float acc[4][4] = {};
#pragma unroll 4
        for (int k = 0; k < DK; k++) {
            float4 b = *(const float4*)&sm[OFF_B + k * SB_STRIDE + i0];
#pragma unroll
            for (int j = 0; j < 4; j++) {
                float a = sm[OFF_A + (m0 + j) * SK_STRIDE + k];
                acc[j][0] += a * b.x; acc[j][1] += a * b.y;
                acc[j][2] += a * b.z; acc[j][3] += a * b.w;
            }
        }
        // write raw logits into sB rows 128+m
#pragma unroll
        for (int j = 0; j < 4; j++)
#pragma unroll
            for (int ii = 0; ii < 4; ii++)
                sm[OFF_B + (128 + m0 + j) * SB_STRIDE + i0 + ii] = acc[j][ii];
    }
    __syncthreads();

    // ---- softmax per column over m<50; zero pad rows 178..191
    if (tid < TI) {
        const int i = tid;
        float mx = -1e30f;
        for (int m = 0; m < MM; m++)
            mx = fmaxf(mx, sm[OFF_B + (128 + m) * SB_STRIDE + i]);
        float s = 0.f;
        for (int m = 0; m < MM; m++) {
            float ev = expf(sm[OFF_B + (128 + m) * SB_STRIDE + i] - mx);
            sm[OFF_B + (128 + m) * SB_STRIDE + i] = ev;
            s += ev;
        }
        float inv = 1.f / s;
        for (int m = 0; m < MM; m++)
            sm[OFF_B + (128 + m) * SB_STRIDE + i] *= inv;
        for (int m = MM; m < TI; m++)
            sm[OFF_B + (128 + m) * SB_STRIDE + i] = 0.f;
    }
    __syncthreads();

    // ---- GEMM2: H[512][64] = [W_f_k | M1] @ sB, fused relu/w_p epilogue
    float pp[4] = {0.f, 0.f, 0.f, 0.f};
    for (int pass = 0; pass < 8; pass++) {
        const int hb = pass * 64;
        // stage A tile [64 h][192 k] (h-major, conflict-free store)
        for (int e = tid; e < 64 * KT; e += 256) {
            int h = e / KT, k = e - h * KT;
            int hg = hb + h;
            float v;
            if (k < DK)            v = Wf[hg * FF + DV + k];       // embed part of W_f
            else { int m = k - DK; v = (m < MM) ? g_M1[hg * MM + m] : 0.f; }
            sm[OFF_A + h * SA_STRIDE + k] = v;
        }
        __syncthreads();

        const int h0 = ty * 4;
        float acc[4][4] = {};
#pragma unroll 4
        for (int k = 0; k < KT; k++) {
            float4 b = *(const float4*)&sm[OFF_B + k * SB_STRIDE + i0];
#pragma unroll
            for (int j = 0; j < 4; j++) {
                float a = sm[OFF_A + (h0 + j) * SA_STRIDE + k];
                acc[j][0] += a * b.x; acc[j][1] += a * b.y;
                acc[j][2] += a * b.z; acc[j][3] += a * b.w;
            }
        }
        // epilogue: bias, relu, weight by w_p, accumulate per-column partials
#pragma unroll
        for (int j = 0; j < 4; j++) {
            int hg = hb + h0 + j;
            float bfv = bf[hg], wpv = Wp[hg];
#pragma unroll
            for (int ii = 0; ii < 4; ii++) {
                float v = acc[j][ii] + bfv;
                pp[ii] += fmaxf(v, 0.f) * wpv;
            }
        }
        __syncthreads();   // protect sA before next pass's staging
    }

    // ---- reduce partials over ty (16), finish sigmoid, write table
#pragma unroll
    for (int ii = 0; ii < 4; ii++)
        sm[OFF_RED + ty * SB_STRIDE + i0 + ii] = pp[ii];
    __syncthreads();
    if (tid < TI) {
        float s = 0.f;
#pragma unroll
        for (int r = 0; r < 16; r++) s += sm[OFF_RED + r * SB_STRIDE + tid];
        s += bp[0];
        float pred = 1.f / (1.f + expf(-s));
        int ridx = base + tid;
        if (ridx < NQ) g_pred[ridx] = pred;
    }
}

// ---------------------------------------------------------------- kernel 2
__global__ void k_gather(const int* __restrict__ q, float* __restrict__ out, int n) {
    int j = blockIdx.x * blockDim.x + threadIdx.x;
    if (j < n) {
        int idx = q[j];
        if (idx < 0) idx = 0;
        if (idx >= NQ) idx = NQ - 1;
        out[j] = g_pred[idx];
    }
}

// ---------------------------------------------------------------- launcher
extern "C" void kernel_launch(void* const* d_in, const int* in_sizes, int n_in,
                              void* d_out, int out_size) {
    const int*   q     = (const int*)  d_in[0];
    const float* Kmem  = (const float*)d_in[2];
    const float* V     = (const float*)d_in[3];
    const float* embed = (const float*)d_in[4];
    const float* Wf    = (const float*)d_in[9];
    const float* bf    = (const float*)d_in[10];
    const float* Wp    = (const float*)d_in[11];
    const float* bp    = (const float*)d_in[12];

    k_m1<<<(HH * MM + 255) / 256, 256>>>(Wf, V);

    cudaFuncSetAttribute(k_main, cudaFuncAttributeMaxDynamicSharedMemorySize,
                         SMEM_FLOATS * (int)sizeof(float));
    k_main<<<(NQ + TI - 1) / TI, 256, SMEM_FLOATS * sizeof(float)>>>(
        embed, Kmem, Wf, bf, Wp, bp);

    k_gather<<<(out_size + 255) / 256, 256>>>(q, (float*)d_out, out_size);
}

// round 2
// speedup vs baseline: 1.8120x; 1.8120x over previous
#include <cuda_runtime.h>

// DKVMN forward, table-over-indices formulation + packed f32x2 FFMA:
//   k_prep  : builds g_A[180][512] = [ W_f_k^T (128 rows) ; M1^T (50 rows) ; 0 (2 rows) ]
//             where M1[h][m] = sum_v W_f[h][v] * V[m][v]
//   k_main  : per 64 table indices i: gather embed -> logits(50x64) -> softmax ->
//             H[512][64] = g_A^T-style GEMM -> pred = sigmoid(w_p . relu(H+b) + b_p)
//   k_gather: out[j] = g_pred[q[j]]

#define NQ   50001
#define DK   128
#define DV   256
#define MM   50
#define HH   512
#define FF   384
#define TI   64
#define KT   180          // 128 embed + 50 corr + 2 zero pad

#define SBS  68           // sB row stride (64 i + pad), 272B = 16B aligned
#define SAS  68           // sA row stride (64 h/m + pad)
#define OFF_B   0
#define OFF_A   (KT * SBS)                 // 12240
#define OFF_RED (OFF_A + KT * SAS)         // 24480
#define SMEM_FLOATS (OFF_RED + 16 * SBS)   // 25568 floats = 102272 B -> 2 CTAs/SM

typedef unsigned long long ull;

__device__ float g_A[KT * HH];
__device__ float g_pred[NQ];

__device__ __forceinline__ ull dup2(float x) {
    ull r; asm("mov.b64 %0, {%1, %1};" : "=l"(r) : "f"(x)); return r;
}
__device__ __forceinline__ void ffma2(ull &d, ull a, ull b) {
    asm("fma.rn.f32x2 %0, %1, %2, %0;" : "+l"(d) : "l"(a), "l"(b));
}
__device__ __forceinline__ float2 unpk(ull p) {
    float2 f; asm("mov.b64 {%0, %1}, %2;" : "=f"(f.x), "=f"(f.y) : "l"(p)); return f;
}

// ---------------------------------------------------------------- prep
__global__ void k_prep(const float* __restrict__ Wf, const float* __restrict__ V) {
    const int b = blockIdx.x, tid = threadIdx.x;
    if (b < 64) {
        // M1 for h in [b*8, b*8+8): 8 x 50 outputs, smem-tiled over v
        __shared__ float sV[MM * 64];
        __shared__ float sW[8 * 64];
        const int hbase = b * 8;
        const int o0 = tid;            // < 400 always
        const int o1 = tid + 256;      // < 400 iff tid < 144
        float acc0 = 0.f, acc1 = 0.f;
        for (int c = 0; c < DV; c += 64) {
            __syncthreads();
            for (int e = tid; e < MM * 64; e += 256) {
                int m = e >> 6, v = e & 63;
                sV[e] = V[m * DV + c + v];
            }
            for (int e = tid; e < 8 * 64; e += 256) {
                int h = e >> 6, v = e & 63;
                sW[e] = Wf[(hbase + h) * FF + c + v];
            }
            __syncthreads();
            {
                int h = o0 / MM, m = o0 - h * MM;
                const float* wr = &sW[h * 64];
                const float* vr = &sV[m * 64];
                float s = 0.f;
#pragma unroll
                for (int v = 0; v < 64; v++) s += wr[v] * vr[v];
                acc0 += s;
            }
            if (o1 < 400) {
                int h = o1 / MM, m = o1 - h * MM;
                const float* wr = &sW[h * 64];
                const float* vr = &sV[m * 64];
                float s = 0.f;
#pragma unroll
                for (int v = 0; v < 64; v++) s += wr[v] * vr[v];
                acc1 += s;
            }
        }
        { int h = o0 / MM, m = o0 - h * MM; g_A[(DK + m) * HH + hbase + h] = acc0; }
        if (o1 < 400) { int h = o1 / MM, m = o1 - h * MM; g_A[(DK + m) * HH + hbase + h] = acc1; }
    } else if (b < 96) {
        // transpose copy: g_A[k][h] = Wf[h][256+k], 65536 elements over 32 blocks
        const int b2 = b - 64;
#pragma unroll
        for (int r = 0; r < 8; r++) {
            int e = b2 * 2048 + r * 256 + tid;
            int k = e >> 9, h = e & 511;
            g_A[k * HH + h] = Wf[h * FF + DV + k];
        }
    } else {
        // zero pad rows 178, 179
        for (int e = tid; e < 2 * HH; e += 256)
            g_A[(DK + MM) * HH + e] = 0.f;
    }
}

// ---------------------------------------------------------------- main
__global__ void __launch_bounds__(256, 2) k_main(
    const float* __restrict__ embed, const float* __restrict__ Kmem,
    const float* __restrict__ bf,    const float* __restrict__ Wp,
    const float* __restrict__ bp)
{
    extern __shared__ float sm[];
    const int tid  = threadIdx.x;
    const int base = blockIdx.x * TI;
    const int col  = tid & 15, row = tid >> 4;
    const int i0   = col * 4;

    // ---- stage sB[k][i] (k<128) from embed (vectorized), zero pad rows 178/179
    for (int e = tid; e < TI * 32; e += 256) {
        int i = e >> 5, kq = e & 31;
        int r = base + i; if (r >= NQ) r = NQ - 1;
        float4 v = *(const float4*)&embed[r * DK + kq * 4];
        int k = kq * 4;
        sm[OFF_B + (k + 0) * SBS + i] = v.x;
        sm[OFF_B + (k + 1) * SBS + i] = v.y;
        sm[OFF_B + (k + 2) * SBS + i] = v.z;
        sm[OFF_B + (k + 3) * SBS + i] = v.w;
    }
    if (tid < 2 * SBS) sm[OFF_B + (DK + MM) * SBS + tid] = 0.f;
    // ---- stage sA = Kmem^T [128][64] with zero m-pad
    for (int e = tid; e < DK * TI; e += 256) {
        int k = e >> 6, m = e & 63;
        sm[OFF_A + k * SAS + m] = (m < MM) ? Kmem[m * DK + k] : 0.f;
    }
    __syncthreads();

    // ---- GEMM1: logits[m][i] = sum_{k<128} K^T[k][m] * E[k][i]
    {
        const int m0 = row * 4;
        ull acc[4][2] = {};
#pragma unroll 4
        for (int k = 0; k < DK; k++) {
            float4    a4 = *(const float4*)   &sm[OFF_A + k * SAS + m0];
            ulonglong2 b2 = *(const ulonglong2*)&sm[OFF_B + k * SBS + i0];
            ull A;
            A = dup2(a4.x); ffma2(acc[0][0], A, b2.x); ffma2(acc[0][1], A, b2.y);
            A = dup2(a4.y); ffma2(acc[1][0], A, b2.x); ffma2(acc[1][1], A, b2.y);
            A = dup2(a4.z); ffma2(acc[2][0], A, b2.x); ffma2(acc[2][1], A, b2.y);
            A = dup2(a4.w); ffma2(acc[3][0], A, b2.x); ffma2(acc[3][1], A, b2.y);
        }
#pragma unroll
        for (int j = 0; j < 4; j++) {
            int m = m0 + j;
            if (m < MM) {
                *(float2*)&sm[OFF_B + (DK + m) * SBS + i0]     = unpk(acc[j][0]);
                *(float2*)&sm[OFF_B + (DK + m) * SBS + i0 + 2] = unpk(acc[j][1]);
            }
        }
    }
    __syncthreads();

    // ---- softmax per column over m<50 (writes probs back into rows 128..177)
    if (tid < TI) {
        float mx = -1e30f;
        for (int m = 0; m < MM; m++)
            mx = fmaxf(mx, sm[OFF_B + (DK + m) * SBS + tid]);
        float s = 0.f;
        for (int m = 0; m < MM; m++) {
            float ev = expf(sm[OFF_B + (DK + m) * SBS + tid] - mx);
            sm[OFF_B + (DK + m) * SBS + tid] = ev;
            s += ev;
        }
        float inv = 1.f / s;
        for (int m = 0; m < MM; m++)
            sm[OFF_B + (DK + m) * SBS + tid] *= inv;
    }
    __syncthreads();

    // ---- GEMM2: 8 passes of 64 h; fused relu / w_p epilogue
    float pp[4] = {0.f, 0.f, 0.f, 0.f};
    const int h0 = row * 4;
    for (int pass = 0; pass < 8; pass++) {
        const int hb = pass * 64;
        for (int e = tid; e < KT * 16; e += 256) {
            int k = e >> 4, j = e & 15;
            *(float4*)&sm[OFF_A + k * SAS + j * 4] =
                *(const float4*)&g_A[k * HH + hb + j * 4];
        }
        __syncthreads();

        ull acc[4][2] = {};
#pragma unroll 4
        for (int k = 0; k < KT; k++) {
            float4     a4 = *(const float4*)   &sm[OFF_A + k * SAS + h0];
            ulonglong2 b2 = *(const ulonglong2*)&sm[OFF_B + k * SBS + i0];
            ull A;
            A = dup2(a4.x); ffma2(acc[0][0], A, b2.x); ffma2(acc[0][1], A, b2.y);
            A = dup2(a4.y); ffma2(acc[1][0], A, b2.x); ffma2(acc[1][1], A, b2.y);
            A = dup2(a4.z); ffma2(acc[2][0], A, b2.x); ffma2(acc[2][1], A, b2.y);
            A = dup2(a4.w); ffma2(acc[3][0], A, b2.x); ffma2(acc[3][1], A, b2.y);
        }
#pragma unroll
        for (int j = 0; j < 4; j++) {
            int hg = hb + h0 + j;
            float bfv = bf[hg], wpv = Wp[hg];
            float2 u0 = unpk(acc[j][0]), u1 = unpk(acc[j][1]);
            pp[0] += fmaxf(u0.x + bfv, 0.f) * wpv;
            pp[1] += fmaxf(u0.y + bfv, 0.f) * wpv;
            pp[2] += fmaxf(u1.x + bfv, 0.f) * wpv;
            pp[3] += fmaxf(u1.y + bfv, 0.f) * wpv;
        }
        __syncthreads();
    }

    // ---- reduce 16 partial rows -> sigmoid -> table
#pragma unroll
    for (int ii = 0; ii < 4; ii++)
        sm[OFF_RED + row * SBS + i0 + ii] = pp[ii];
    __syncthreads();
    if (tid < TI) {
        float s = 0.f;
#pragma unroll
        for (int r2 = 0; r2 < 16; r2++) s += sm[OFF_RED + r2 * SBS + tid];
        s += bp[0];
        int ridx = base + tid;
        if (ridx < NQ) g_pred[ridx] = 1.f / (1.f + expf(-s));
    }
}

// ---------------------------------------------------------------- gather
__global__ void k_gather(const int* __restrict__ q, float* __restrict__ out, int n) {
    int j = blockIdx.x * blockDim.x + threadIdx.x;
    if (j < n) {
        int idx = q[j];
        if (idx < 0) idx = 0;
        if (idx >= NQ) idx = NQ - 1;
        out[j] = g_pred[idx];
    }
}

// ---------------------------------------------------------------- launcher
extern "C" void kernel_launch(void* const* d_in, const int* in_sizes, int n_in,
                              void* d_out, int out_size) {
    const int*   q     = (const int*)  d_in[0];
    const float* Kmem  = (const float*)d_in[2];
    const float* V     = (const float*)d_in[3];
    const float* embed = (const float*)d_in[4];
    const float* Wf    = (const float*)d_in[9];
    const float* bf    = (const float*)d_in[10];
    const float* Wp    = (const float*)d_in[11];
    const float* bp    = (const float*)d_in[12];

    k_prep<<<97, 256>>>(Wf, V);

    cudaFuncSetAttribute(k_main, cudaFuncAttributeMaxDynamicSharedMemorySize,
                         SMEM_FLOATS * (int)sizeof(float));
    k_main<<<(NQ + TI - 1) / TI, 256, SMEM_FLOATS * sizeof(float)>>>(
        embed, Kmem, bf, Wp, bp);

    k_gather<<<(out_size + 255) / 256, 256>>>(q, (float*)d_out, out_size);
}

// round 3
// speedup vs baseline: 1.8137x; 1.0010x over previous
#include <cuda_runtime.h>

// DKVMN forward, table-over-indices formulation + packed f32x2 FFMA:
//   k_prep  : builds g_A[180][512] = [ W_f_k^T (128 rows) ; M1^T (50 rows) ; 0 (2 rows) ]
//             where M1[h][m] = sum_v W_f[h][v] * V[m][v]
//   k_main  : per 64 table indices i: gather embed -> logits(50x64) -> softmax ->
//             H[512][64] = g_A^T-style GEMM -> pred = sigmoid(w_p . relu(H+b) + b_p)
//   k_gather: out[j] = g_pred[q[j]]

#define NQ   50001
#define DK   128
#define DV   256
#define MM   50
#define HH   512
#define FF   384
#define TI   64
#define KT   180          // 128 embed + 50 corr + 2 zero pad

#define SBS  68           // sB row stride (64 i + pad), 272B = 16B aligned
#define SAS  68           // sA row stride (64 h/m + pad)
#define OFF_B   0
#define OFF_A   (KT * SBS)                 // 12240
#define OFF_RED (OFF_A + KT * SAS)         // 24480
#define SMEM_FLOATS (OFF_RED + 16 * SBS)   // 25568 floats = 102272 B -> 2 CTAs/SM

typedef unsigned long long ull;

__device__ float g_A[KT * HH];
__device__ float g_pred[NQ];

__device__ __forceinline__ ull dup2(float x) {
    ull r; asm("mov.b64 %0, {%1, %1};" : "=l"(r) : "f"(x)); return r;
}
__device__ __forceinline__ void ffma2(ull &d, ull a, ull b) {
    asm("fma.rn.f32x2 %0, %1, %2, %0;" : "+l"(d) : "l"(a), "l"(b));
}
__device__ __forceinline__ float2 unpk(ull p) {
    float2 f; asm("mov.b64 {%0, %1}, %2;" : "=f"(f.x), "=f"(f.y) : "l"(p)); return f;
}

// ---------------------------------------------------------------- prep
__global__ void k_prep(const float* __restrict__ Wf, const float* __restrict__ V) {
    const int b = blockIdx.x, tid = threadIdx.x;
    if (b < 64) {
        // M1 for h in [b*8, b*8+8): 8 x 50 outputs, smem-tiled over v
        __shared__ float sV[MM * 64];
        __shared__ float sW[8 * 64];
        const int hbase = b * 8;
        const int o0 = tid;            // < 400 always
        const int o1 = tid + 256;      // < 400 iff tid < 144
        float acc0 = 0.f, acc1 = 0.f;
        for (int c = 0; c < DV; c += 64) {
            __syncthreads();
            for (int e = tid; e < MM * 64; e += 256) {
                int m = e >> 6, v = e & 63;
                sV[e] = V[m * DV + c + v];
            }
            for (int e = tid; e < 8 * 64; e += 256) {
                int h = e >> 6, v = e & 63;
                sW[e] = Wf[(hbase + h) * FF + c + v];
            }
            __syncthreads();
            {
                int h = o0 / MM, m = o0 - h * MM;
                const float* wr = &sW[h * 64];
                const float* vr = &sV[m * 64];
                float s = 0.f;
#pragma unroll
                for (int v = 0; v < 64; v++) s += wr[v] * vr[v];
                acc0 += s;
            }
            if (o1 < 400) {
                int h = o1 / MM, m = o1 - h * MM;
                const float* wr = &sW[h * 64];
                const float* vr = &sV[m * 64];
                float s = 0.f;
#pragma unroll
                for (int v = 0; v < 64; v++) s += wr[v] * vr[v];
                acc1 += s;
            }
        }
        { int h = o0 / MM, m = o0 - h * MM; g_A[(DK + m) * HH + hbase + h] = acc0; }
        if (o1 < 400) { int h = o1 / MM, m = o1 - h * MM; g_A[(DK + m) * HH + hbase + h] = acc1; }
    } else if (b < 96) {
        // transpose copy: g_A[k][h] = Wf[h][256+k], 65536 elements over 32 blocks
        const int b2 = b - 64;
#pragma unroll
        for (int r = 0; r < 8; r++) {
            int e = b2 * 2048 + r * 256 + tid;
            int k = e >> 9, h = e & 511;
            g_A[k * HH + h] = Wf[h * FF + DV + k];
        }
    } else {
        // zero pad rows 178, 179
        for (int e = tid; e < 2 * HH; e += 256)
            g_A[(DK + MM) * HH + e] = 0.f;
    }
}

// ---------------------------------------------------------------- main
__global__ void __launch_bounds__(256, 2) k_main(
    const float* __restrict__ embed, const float* __restrict__ Kmem,
    const float* __restrict__ bf,    const float* __restrict__ Wp,
    const float* __restrict__ bp)
{
    extern __shared__ float sm[];
    const int tid  = threadIdx.x;
    const int base = blockIdx.x * TI;
    const int col  = tid & 15, row = tid >> 4;
    const int i0   = col * 4;

    // ---- stage sB[k][i] (k<128) from embed (vectorized), zero pad rows 178/179
    for (int e = tid; e < TI * 32; e += 256) {
        int i = e >> 5, kq = e & 31;
        int r = base + i; if (r >= NQ) r = NQ - 1;
        float4 v = *(const float4*)&embed[r * DK + kq * 4];
        int k = kq * 4;
        sm[OFF_B + (k + 0) * SBS + i] = v.x;
        sm[OFF_B + (k + 1) * SBS + i] = v.y;
        sm[OFF_B + (k + 2) * SBS + i] = v.z;
        sm[OFF_B + (k + 3) * SBS + i] = v.w;
    }
    if (tid < 2 * SBS) sm[OFF_B + (DK + MM) * SBS + tid] = 0.f;
    // ---- stage sA = Kmem^T [128][64] with zero m-pad
    for (int e = tid; e < DK * TI; e += 256) {
        int k = e >> 6, m = e & 63;
        sm[OFF_A + k * SAS + m] = (m < MM) ? Kmem[m * DK + k] : 0.f;
    }
    __syncthreads();

    // ---- GEMM1: logits[m][i] = sum_{k<128} K^T[k][m] * E[k][i]
    {
        const int m0 = row * 4;
        ull acc[4][2] = {};
#pragma unroll 4
        for (int k = 0; k < DK; k++) {
            float4    a4 = *(const float4*)   &sm[OFF_A + k * SAS + m0];
            ulonglong2 b2 = *(const ulonglong2*)&sm[OFF_B + k * SBS + i0];
            ull A;
            A = dup2(a4.x); ffma2(acc[0][0], A, b2.x); ffma2(acc[0][1], A, b2.y);
            A = dup2(a4.y); ffma2(acc[1][0], A, b2.x); ffma2(acc[1][1], A, b2.y);
            A = dup2(a4.z); ffma2(acc[2][0], A, b2.x); ffma2(acc[2][1], A, b2.y);
            A = dup2(a4.w); ffma2(acc[3][0], A, b2.x); ffma2(acc[3][1], A, b2.y);
        }
#pragma unroll
        for (int j = 0; j < 4; j++) {
            int m = m0 + j;
            if (m < MM) {
                *(float2*)&sm[OFF_B + (DK + m) * SBS + i0]     = unpk(acc[j][0]);
                *(float2*)&sm[OFF_B + (DK + m) * SBS + i0 + 2] = unpk(acc[j][1]);
            }
        }
    }
    __syncthreads();

    // ---- softmax per column over m<50 (writes probs back into rows 128..177)
    if (tid < TI) {
        float mx = -1e30f;
        for (int m = 0; m < MM; m++)
            mx = fmaxf(mx, sm[OFF_B + (DK + m) * SBS + tid]);
        float s = 0.f;
        for (int m = 0; m < MM; m++) {
            float ev = expf(sm[OFF_B + (DK + m) * SBS + tid] - mx);
            sm[OFF_B + (DK + m) * SBS + tid] = ev;
            s += ev;
        }
        float inv = 1.f / s;
        for (int m = 0; m < MM; m++)
            sm[OFF_B + (DK + m) * SBS + tid] *= inv;
    }
    __syncthreads();

    // ---- GEMM2: 8 passes of 64 h; fused relu / w_p epilogue
    float pp[4] = {0.f, 0.f, 0.f, 0.f};
    const int h0 = row * 4;
    for (int pass = 0; pass < 8; pass++) {
        const int hb = pass * 64;
        for (int e = tid; e < KT * 16; e += 256) {
            int k = e >> 4, j = e & 15;
            *(float4*)&sm[OFF_A + k * SAS + j * 4] =
                *(const float4*)&g_A[k * HH + hb + j * 4];
        }
        __syncthreads();

        ull acc[4][2] = {};
#pragma unroll 4
        for (int k = 0; k < KT; k++) {
            float4     a4 = *(const float4*)   &sm[OFF_A + k * SAS + h0];
            ulonglong2 b2 = *(const ulonglong2*)&sm[OFF_B + k * SBS + i0];
            ull A;
            A = dup2(a4.x); ffma2(acc[0][0], A, b2.x); ffma2(acc[0][1], A, b2.y);
            A = dup2(a4.y); ffma2(acc[1][0], A, b2.x); ffma2(acc[1][1], A, b2.y);
            A = dup2(a4.z); ffma2(acc[2][0], A, b2.x); ffma2(acc[2][1], A, b2.y);
            A = dup2(a4.w); ffma2(acc[3][0], A, b2.x); ffma2(acc[3][1], A, b2.y);
        }
#pragma unroll
        for (int j = 0; j < 4; j++) {
            int hg = hb + h0 + j;
            float bfv = bf[hg], wpv = Wp[hg];
            float2 u0 = unpk(acc[j][0]), u1 = unpk(acc[j][1]);
            pp[0] += fmaxf(u0.x + bfv, 0.f) * wpv;
            pp[1] += fmaxf(u0.y + bfv, 0.f) * wpv;
            pp[2] += fmaxf(u1.x + bfv, 0.f) * wpv;
            pp[3] += fmaxf(u1.y + bfv, 0.f) * wpv;
        }
        __syncthreads();
    }

    // ---- reduce 16 partial rows -> sigmoid -> table
#pragma unroll
    for (int ii = 0; ii < 4; ii++)
        sm[OFF_RED + row * SBS + i0 + ii] = pp[ii];
    __syncthreads();
    if (tid < TI) {
        float s = 0.f;
#pragma unroll
        for (int r2 = 0; r2 < 16; r2++) s += sm[OFF_RED + r2 * SBS + tid];
        s += bp[0];
        int ridx = base + tid;
        if (ridx < NQ) g_pred[ridx] = 1.f / (1.f + expf(-s));
    }
}

// ---------------------------------------------------------------- gather
__global__ void k_gather(const int* __restrict__ q, float* __restrict__ out, int n) {
    int j = blockIdx.x * blockDim.x + threadIdx.x;
    if (j < n) {
        int idx = q[j];
        if (idx < 0) idx = 0;
        if (idx >= NQ) idx = NQ - 1;
        out[j] = g_pred[idx];
    }
}

// ---------------------------------------------------------------- launcher
extern "C" void kernel_launch(void* const* d_in, const int* in_sizes, int n_in,
                              void* d_out, int out_size) {
    const int*   q     = (const int*)  d_in[0];
    const float* Kmem  = (const float*)d_in[2];
    const float* V     = (const float*)d_in[3];
    const float* embed = (const float*)d_in[4];
    const float* Wf    = (const float*)d_in[9];
    const float* bf    = (const float*)d_in[10];
    const float* Wp    = (const float*)d_in[11];
    const float* bp    = (const float*)d_in[12];

    k_prep<<<97, 256>>>(Wf, V);

    cudaFuncSetAttribute(k_main, cudaFuncAttributeMaxDynamicSharedMemorySize,
                         SMEM_FLOATS * (int)sizeof(float));
    k_main<<<(NQ + TI - 1) / TI, 256, SMEM_FLOATS * sizeof(float)>>>(
        embed, Kmem, bf, Wp, bp);

    k_gather<<<(out_size + 255) / 256, 256>>>(q, (float*)d_out, out_size);
}

// round 5
// speedup vs baseline: 4.5126x; 2.4881x over previous
#include <cuda_runtime.h>
#include <cuda_bf16.h>
#include <cstdint>

#define NQ 50001
#define TI 128
#define NBLK 391

// feat smem row: [hi bf16 k0..191 | lo bf16 k0..191 | pad16] = 784 B
#define ROWB 784
#define SM_FEAT 0
#define SM_L    (SM_FEAT + 128 * ROWB)        // logits [128 i][65 f]
#define SM_PART (SM_L + 128 * 65 * 4)         // partials [8][128] f
#define SM_TOTAL (SM_PART + 8 * 128 * 4)      // 137,728 B

__device__ float g_M1f[512 * 50];
__device__ uint4 g_WA[384 * 2 * 32];          // [(s*4+c)*12+t][term][lane] A-frags (W)
__device__ uint4 g_KA[32 * 2 * 32];           // [c*8+t][term][lane] A-frags (Kmem)
__device__ float g_pred[NQ];

__device__ __forceinline__ uint16_t bhi(float x) {
    return __bfloat16_as_ushort(__float2bfloat16(x));
}
__device__ __forceinline__ uint16_t blo(float x) {
    float h = __bfloat162float(__float2bfloat16(x));
    return __bfloat16_as_ushort(__float2bfloat16(x - h));
}
__device__ __forceinline__ uint32_t pk2(uint16_t a, uint16_t b) {
    return (uint32_t)a | ((uint32_t)b << 16);
}
__device__ __forceinline__ uint32_t s2u(const void* p) {
    uint32_t a;
    asm("{ .reg .u64 t; cvta.to.shared.u64 t, %1; cvt.u32.u64 %0, t; }" : "=r"(a) : "l"(p));
    return a;
}
__device__ __forceinline__ void ldm4(uint32_t addr, uint32_t* r) {
    asm volatile("ldmatrix.sync.aligned.m8n8.x4.shared.b16 {%0,%1,%2,%3}, [%4];"
                 : "=r"(r[0]), "=r"(r[1]), "=r"(r[2]), "=r"(r[3]) : "r"(addr));
}
__device__ __forceinline__ void mma16816(float* c, const uint32_t* a, uint32_t b0, uint32_t b1) {
    asm volatile("mma.sync.aligned.m16n8k16.row.col.f32.bf16.bf16.f32 "
                 "{%0,%1,%2,%3}, {%4,%5,%6,%7}, {%8,%9}, {%0,%1,%2,%3};"
                 : "+f"(c[0]), "+f"(c[1]), "+f"(c[2]), "+f"(c[3])
                 : "r"(a[0]), "r"(a[1]), "r"(a[2]), "r"(a[3]), "r"(b0), "r"(b1));
}
// per-lane ldmatrix address for B tile-pair (i0..i0+15) x (k-step bytes kb0..+31)
__device__ __forceinline__ uint32_t baddr(uint32_t fb, int lane, int i0, int kb0) {
    int row = i0 + (lane & 7) + ((lane & 16) ? 8 : 0);
    int col = (lane & 8) ? 16 : 0;
    return fb + row * ROWB + kb0 + col;
}

// ---------------------------------------------------------------- prep1: M1
__global__ void k_prep1(const float* __restrict__ Wf, const float* __restrict__ V) {
    __shared__ float wrow[256];
    const int b = blockIdx.x, t = threadIdx.x;   // 512 x 64
    for (int e = t; e < 256; e += 64) wrow[e] = Wf[b * 384 + e];
    __syncthreads();
    if (t < 50) {
        const float* vp = V + t * 256;
        float s = 0.f;
#pragma unroll 8
        for (int v = 0; v < 256; v++) s += wrow[v] * __ldg(vp + v);
        g_M1f[b * 50 + t] = s;
    }
}

// ---------------------------------------------------------------- prep2: frag pack
__global__ void k_prep2(const float* __restrict__ Wf, const float* __restrict__ Km) {
    const int b = blockIdx.x, lane = threadIdx.x;   // 416 x 32
    const int q = lane >> 2, r = lane & 3;
    if (b < 384) {
        const int s = b / 48, rem = b % 48, c = rem / 12, t = rem % 12;
        const int h0 = s * 64 + c * 16 + q, h1 = h0 + 8;
        const int k0 = t * 16 + 2 * r;
        float v[8];
#pragma unroll
        for (int j = 0; j < 8; j++) {
            int h = (j & 1) ? h1 : h0;          // j:{a0.x,a1.x,a0.y.. } pattern below
            int k = k0 + ((j >> 2) ? 8 : 0) + ((j >> 1) & 1);
            // order: j = (khalf<<2) | (col<<1) | rowsel
            v[j] = (k < 128) ? Wf[h * 384 + 256 + k]
                             : ((k < 178) ? g_M1f[h * 50 + (k - 128)] : 0.f);
        }
        // a0=(h0,k0),(h0,k0+1) ; a1=(h1,k0),(h1,k0+1) ; a2=(h0,k0+8),(h0,k0+9) ; a3=(h1,...)
        uint4 hi, lo;
        hi.x = pk2(bhi(v[0]), bhi(v[2]));  lo.x = pk2(blo(v[0]), blo(v[2]));
        hi.y = pk2(bhi(v[1]), bhi(v[3]));  lo.y = pk2(blo(v[1]), blo(v[3]));
        hi.z = pk2(bhi(v[4]), bhi(v[6]));  lo.z = pk2(blo(v[4]), blo(v[6]));
        hi.w = pk2(bhi(v[5]), bhi(v[7]));  lo.w = pk2(blo(v[5]), blo(v[7]));
        const int fs = (s * 4 + c) * 12 + t;
        g_WA[(fs * 2 + 0) * 32 + lane] = hi;
        g_WA[(fs * 2 + 1) * 32 + lane] = lo;
    } else {
        const int kb = b - 384, c = kb / 8, t = kb % 8;
        const int m0 = c * 16 + q, m1 = m0 + 8;
        const int k0 = t * 16 + 2 * r;
        float v[8];
#pragma unroll
        for (int j = 0; j < 8; j++) {
            int m = (j & 1) ? m1 : m0;
            int k = k0 + ((j >> 2) ? 8 : 0) + ((j >> 1) & 1);
            v[j] = (m < 50) ? Km[m * 128 + k] : 0.f;
        }
        uint4 hi, lo;
        hi.x = pk2(bhi(v[0]), bhi(v[2]));  lo.x = pk2(blo(v[0]), blo(v[2]));
        hi.y = pk2(bhi(v[1]), bhi(v[3]));  lo.y = pk2(blo(v[1]), blo(v[3]));
        hi.z = pk2(bhi(v[4]), bhi(v[6]));  lo.z = pk2(blo(v[4]), blo(v[6]));
        hi.w = pk2(bhi(v[5]), bhi(v[7]));  lo.w = pk2(blo(v[5]), blo(v[7]));
        const int fs = c * 8 + t;
        g_KA[(fs * 2 + 0) * 32 + lane] = hi;
        g_KA[(fs * 2 + 1) * 32 + lane] = lo;
    }
}

// ---------------------------------------------------------------- main
__global__ void __launch_bounds__(256) k_main(
    const float* __restrict__ embed, const float* __restrict__ bf,
    const float* __restrict__ Wp,    const float* __restrict__ bp)
{
    extern __shared__ __align__(16) unsigned char sm[];
    const int tid = threadIdx.x, wid = tid >> 5, lane = tid & 31;
    const int q = lane >> 2, r = lane & 3;
    const int base = blockIdx.x * TI;
    const uint32_t fb = s2u(sm) + SM_FEAT;
    float* L    = (float*)(sm + SM_L);
    float* part = (float*)(sm + SM_PART);

    // ---- stage embed -> feat rows (hi/lo bf16) ----
    for (int id = tid; id < 4096; id += 256) {
        int row = id >> 5, kq = id & 31;
        int rr = base + row; if (rr >= NQ) rr = NQ - 1;
        float4 v = __ldg((const float4*)&embed[rr * 128 + kq * 4]);
        uint2 h = make_uint2(pk2(bhi(v.x), bhi(v.y)), pk2(bhi(v.z), bhi(v.w)));
        uint2 l = make_uint2(pk2(blo(v.x), blo(v.y)), pk2(blo(v.z), blo(v.w)));
        *(uint2*)(sm + SM_FEAT + row * ROWB + kq * 8)       = h;
        *(uint2*)(sm + SM_FEAT + row * ROWB + 384 + kq * 8) = l;
    }
    if (tid < 128) {    // zero k = 128..191 (hi bytes 256..384, lo 640..768)
        uint4 z = make_uint4(0, 0, 0, 0);
#pragma unroll
        for (int j = 0; j < 8; j++) {
            *(uint4*)(sm + SM_FEAT + tid * ROWB + 256 + j * 16) = z;
            *(uint4*)(sm + SM_FEAT + tid * ROWB + 640 + j * 16) = z;
        }
    }
    __syncthreads();

    // ---- GEMM1: logits[m 64][i 128] = Kmem . feat^T ----
    {
        const int c = wid & 3, half = wid >> 2, ib = half * 64;
        float cf[8][4];
#pragma unroll
        for (int n = 0; n < 8; n++)
#pragma unroll
            for (int j = 0; j < 4; j++) cf[n][j] = 0.f;
#pragma unroll
        for (int t = 0; t < 8; t++) {
            uint4 fah = __ldg(&g_KA[((c * 8 + t) * 2 + 0) * 32 + lane]);
            uint4 fal = __ldg(&g_KA[((c * 8 + t) * 2 + 1) * 32 + lane]);
            uint32_t ah[4] = {fah.x, fah.y, fah.z, fah.w};
            uint32_t al[4] = {fal.x, fal.y, fal.z, fal.w};
#pragma unroll
            for (int n2 = 0; n2 < 4; n2++) {
                uint32_t bh[4], bl[4];
                ldm4(baddr(fb, lane, ib + n2 * 16, t * 32), bh);
                ldm4(baddr(fb, lane, ib + n2 * 16, 384 + t * 32), bl);
                mma16816(cf[n2 * 2],     ah, bh[0], bh[1]);
                mma16816(cf[n2 * 2],     al, bh[0], bh[1]);
                mma16816(cf[n2 * 2],     ah, bl[0], bl[1]);
                mma16816(cf[n2 * 2 + 1], ah, bh[2], bh[3]);
                mma16816(cf[n2 * 2 + 1], al, bh[2], bh[3]);
                mma16816(cf[n2 * 2 + 1], ah, bl[2], bl[3]);
            }
        }
        // scatter logits: C[m][i] -> L[i][m]
        const int m0 = c * 16 + q;
#pragma unroll
        for (int n = 0; n < 8; n++) {
            int i = ib + n * 8 + 2 * r;
            L[i * 65 + m0]           = cf[n][0];
            L[(i + 1) * 65 + m0]     = cf[n][1];
            L[i * 65 + m0 + 8]       = cf[n][2];
            L[(i + 1) * 65 + m0 + 8] = cf[n][3];
        }
    }
    __syncthreads();

    // ---- softmax per i (thread = one i), write probs into feat k=128..177 ----
    if (tid < 128) {
        const float* row = &L[tid * 65];
        float lg[50], mx = -1e30f;
#pragma unroll
        for (int m = 0; m < 50; m++) { lg[m] = row[m]; mx = fmaxf(mx, lg[m]); }
        float s = 0.f;
#pragma unroll
        for (int m = 0; m < 50; m++) { lg[m] = __expf(lg[m] - mx); s += lg[m]; }
        float inv = 1.f / s;
#pragma unroll
        for (int j = 0; j < 25; j++) {
            float p0 = lg[2 * j] * inv, p1 = lg[2 * j + 1] * inv;
            *(uint32_t*)(sm + SM_FEAT + tid * ROWB + 256 + 4 * j)       = pk2(bhi(p0), bhi(p1));
            *(uint32_t*)(sm + SM_FEAT + tid * ROWB + 640 + 4 * j)       = pk2(blo(p0), blo(p1));
        }
    }
    __syncthreads();

    // ---- GEMM2: H[512][128] in 8 strips x 4 chunks; fused relu/wp epilogue ----
    {
        const int s = wid;
        float pacc[32];
#pragma unroll
        for (int j = 0; j < 32; j++) pacc[j] = 0.f;
        for (int c = 0; c < 4; c++) {
            float cf[16][4];
#pragma unroll
            for (int n = 0; n < 16; n++)
#pragma unroll
                for (int j = 0; j < 4; j++) cf[n][j] = 0.f;
#pragma unroll
            for (int t = 0; t < 12; t++) {
                const int fs = (s * 4 + c) * 12 + t;
                uint4 fah = __ldg(&g_WA[(fs * 2 + 0) * 32 + lane]);
                uint4 fal = __ldg(&g_WA[(fs * 2 + 1) * 32 + lane]);
                uint32_t ah[4] = {fah.x, fah.y, fah.z, fah.w};
                uint32_t al[4] = {fal.x, fal.y, fal.z, fal.w};
#pragma unroll
                for (int n2 = 0; n2 < 8; n2++) {
                    uint32_t bh[4], bl[4];
                    ldm4(baddr(fb, lane, n2 * 16, t * 32), bh);
                    ldm4(baddr(fb, lane, n2 * 16, 384 + t * 32), bl);
                    mma16816(cf[n2 * 2],     ah, bh[0], bh[1]);
                    mma16816(cf[n2 * 2],     al, bh[0], bh[1]);
                    mma16816(cf[n2 * 2],     ah, bl[0], bl[1]);
                    mma16816(cf[n2 * 2 + 1], ah, bh[2], bh[3]);
                    mma16816(cf[n2 * 2 + 1], al, bh[2], bh[3]);
                    mma16816(cf[n2 * 2 + 1], ah, bl[2], bl[3]);
                }
            }
            const int h0 = s * 64 + c * 16 + q, h1 = h0 + 8;
            float b0 = __ldg(&bf[h0]), b1 = __ldg(&bf[h1]);
            float w0 = __ldg(&Wp[h0]), w1 = __ldg(&Wp[h1]);
#pragma unroll
            for (int n = 0; n < 16; n++) {
                pacc[2 * n]     += fmaxf(cf[n][0] + b0, 0.f) * w0 + fmaxf(cf[n][2] + b1, 0.f) * w1;
                pacc[2 * n + 1] += fmaxf(cf[n][1] + b0, 0.f) * w0 + fmaxf(cf[n][3] + b1, 0.f) * w1;
            }
        }
        // reduce over the 8 lanes sharing lane%4
#pragma unroll
        for (int j = 0; j < 32; j++) {
            pacc[j] += __shfl_xor_sync(0xffffffffu, pacc[j], 4);
            pacc[j] += __shfl_xor_sync(0xffffffffu, pacc[j], 8);
            pacc[j] += __shfl_xor_sync(0xffffffffu, pacc[j], 16);
        }
        if (lane < 4) {
#pragma unroll
            for (int n = 0; n < 16; n++) {
                int i = n * 8 + 2 * lane;
                part[s * 128 + i]     = pacc[2 * n];
                part[s * 128 + i + 1] = pacc[2 * n + 1];
            }
        }
    }
    __syncthreads();

    // ---- final reduce + sigmoid ----
    if (tid < 128) {
        float sum = __ldg(bp);
#pragma unroll
        for (int s = 0; s < 8; s++) sum += part[s * 128 + tid];
        int rr = base + tid;
        if (rr < NQ) g_pred[rr] = 1.f / (1.f + __expf(-sum));
    }
}

// ---------------------------------------------------------------- gather
__global__ void k_gather(const int* __restrict__ q, float* __restrict__ out, int n) {
    int j = (blockIdx.x * blockDim.x + threadIdx.x) * 4;
    if (j + 3 < n) {
        int4 qv = *(const int4*)(q + j);
        float4 o;
        o.x = g_pred[(unsigned)qv.x < NQ ? qv.x : NQ - 1];
        o.y = g_pred[(unsigned)qv.y < NQ ? qv.y : NQ - 1];
        o.z = g_pred[(unsigned)qv.z < NQ ? qv.z : NQ - 1];
        o.w = g_pred[(unsigned)qv.w < NQ ? qv.w : NQ - 1];
        *(float4*)(out + j) = o;
    } else {
        for (; j < n; j++) {
            int idx = q[j];
            out[j] = g_pred[(unsigned)idx < NQ ? idx : NQ - 1];
        }
    }
}

// ---------------------------------------------------------------- launcher
extern "C" void kernel_launch(void* const* d_in, const int* in_sizes, int n_in,
                              void* d_out, int out_size) {
    const int*   q     = (const int*)  d_in[0];
    const float* Kmem  = (const float*)d_in[2];
    const float* V     = (const float*)d_in[3];
    const float* embed = (const float*)d_in[4];
    const float* Wf    = (const float*)d_in[9];
    const float* bf    = (const float*)d_in[10];
    const float* Wp    = (const float*)d_in[11];
    const float* bp    = (const float*)d_in[12];

    k_prep1<<<512, 64>>>(Wf, V);
    k_prep2<<<416, 32>>>(Wf, Kmem);

    cudaFuncSetAttribute(k_main, cudaFuncAttributeMaxDynamicSharedMemorySize, SM_TOTAL);
    k_main<<<NBLK, 256, SM_TOTAL>>>(embed, bf, Wp, bp);

    k_gather<<<(out_size + 1023) / 1024, 256>>>(q, (float*)d_out, out_size);
}